// round 2
// baseline (speedup 1.0000x reference)
#include <cuda_runtime.h>
#include <math.h>
#include <stdint.h>

#define NBATCH 4
#define NCH    180
#define IMG    256
#define NPIX   (IMG*IMG)            // 65536
#define TOTPIX (NBATCH*NPIX)        // 262144
#define MIDC   36
#define NHEAD  6
#define HDIM   15
#define WL     256                  // window length 16x16
#define NWIN   1024

// ---- scratch (device globals; no allocation allowed) ----
__device__ float g_h1[(size_t)TOTPIX*MIDC];
__device__ float g_h2[(size_t)TOTPIX*MIDC];
__device__ float g_qv[(size_t)TOTPIX*NCH];
__device__ float g_y [(size_t)TOTPIX*NCH];
__device__ float g_pos[961*6];
__device__ float g_rpb[6*256*64];

__device__ __forceinline__ float lrelu(float v){ return v >= 0.f ? v : 0.2f*v; }

// =============== K0a: position-bias MLP (961 rows) ===============
__device__ __forceinline__ void ln_relu11(const float* in, const float* w, const float* b, float* out){
  float m = 0.f;
#pragma unroll
  for (int j=0;j<11;j++) m += in[j];
  m *= (1.f/11.f);
  float var = 0.f;
#pragma unroll
  for (int j=0;j<11;j++){ float d = in[j]-m; var += d*d; }
  var *= (1.f/11.f);
  float inv = rsqrtf(var + 1e-5f);
#pragma unroll
  for (int j=0;j<11;j++) out[j] = fmaxf((in[j]-m)*inv*w[j] + b[j], 0.f);
}

__global__ void k_pos(const float* __restrict__ pw, const float* __restrict__ pb,
                      const float* __restrict__ ln1w, const float* __restrict__ ln1b,
                      const float* __restrict__ w1,  const float* __restrict__ b1,
                      const float* __restrict__ ln2w, const float* __restrict__ ln2b,
                      const float* __restrict__ w2,  const float* __restrict__ b2,
                      const float* __restrict__ ln3w, const float* __restrict__ ln3b,
                      const float* __restrict__ w3,  const float* __restrict__ b3){
  int n = blockIdx.x*blockDim.x + threadIdx.x;
  if (n >= 961) return;
  float i0 = (float)(n/31) - 15.f;
  float i1 = (float)(n%31) - 15.f;
  float p[11], t[11];
#pragma unroll
  for (int j=0;j<11;j++) p[j] = i0*pw[j] + i1*pw[11+j] + pb[j];
  ln_relu11(p, ln1w, ln1b, t);
#pragma unroll
  for (int k=0;k<11;k++){ float s=b1[k];
#pragma unroll
    for (int j=0;j<11;j++) s += t[j]*w1[j*11+k]; p[k]=s; }
  ln_relu11(p, ln2w, ln2b, t);
#pragma unroll
  for (int k=0;k<11;k++){ float s=b2[k];
#pragma unroll
    for (int j=0;j<11;j++) s += t[j]*w2[j*11+k]; p[k]=s; }
  ln_relu11(p, ln3w, ln3b, t);
#pragma unroll
  for (int k=0;k<6;k++){ float s=b3[k];
#pragma unroll
    for (int j=0;j<11;j++) s += t[j]*w3[j*6+k];
    g_pos[n*6+k] = s; }
}

// =============== K0b: rpb[nh][l][m] = mean over 2x2 of pos ===============
__global__ void k_rpb(){
  int idx = blockIdx.x*blockDim.x + threadIdx.x;
  if (idx >= 6*256*64) return;
  int nh = idx/16384;
  int r  = idx - nh*16384;
  int l  = r>>6;
  int m  = r&63;
  int rl = l>>4, cl = l&15;
  int mh = m>>3, mw = m&7;
  float s = 0.f;
#pragma unroll
  for (int rh=0;rh<2;rh++)
#pragma unroll
    for (int rw=0;rw<2;rw++){
      int r2 = mh*2+rh, c2 = mw*2+rw;
      int k = (rl-r2+15)*31 + (cl-c2+15);
      s += g_pos[k*6+nh];
    }
  g_rpb[idx] = 0.25f*s;
}

// =============== K1: h1 = lrelu(x @ w1 + b1), 180->36, NCHW in, NHWC out ===============
__global__ void __launch_bounds__(256) k_dfe1(const float* __restrict__ x,
                                              const float* __restrict__ w1,
                                              const float* __restrict__ b1){
  __shared__ float ws[180*36];
  int tid = threadIdx.x;
  for (int t=tid;t<180*36;t+=256) ws[t]=w1[t];
  __syncthreads();
  int r = blockIdx.x*256 + tid;
  int b = r>>16; int p = r&65535;
  const float* xp = x + (size_t)b*NCH*NPIX + p;
  float acc[36];
#pragma unroll
  for (int co=0;co<36;co++) acc[co] = b1[co];
  for (int ci=0;ci<180;ci++){
    float v = xp[(size_t)ci*NPIX];
    const float* wr = ws + ci*36;
#pragma unroll
    for (int co=0;co<36;co++) acc[co] += v*wr[co];
  }
  float4* dst = (float4*)(g_h1 + (size_t)r*36);
#pragma unroll
  for (int q=0;q<9;q++){
    float4 o; o.x=lrelu(acc[q*4]); o.y=lrelu(acc[q*4+1]); o.z=lrelu(acc[q*4+2]); o.w=lrelu(acc[q*4+3]);
    dst[q]=o;
  }
}

// =============== K2: h2 = lrelu(conv3x3(h1)), 36->36, NHWC ===============
__global__ void __launch_bounds__(256) k_conv3(const float* __restrict__ w2,
                                               const float* __restrict__ b2){
  extern __shared__ float sm2[];
  float* ins = sm2;             // 18*18*37 = 11988 floats
  float* wsh = sm2 + 11988;     // 9*36*36  = 11664 floats
  int tid = threadIdx.x;
  int b = blockIdx.z; int hy0 = blockIdx.y*16, wx0 = blockIdx.x*16;
  for (int t=tid;t<18*18*36;t+=256){
    int ci = t%36; int rc = t/36; int col = rc%18; int row = rc/18;
    int gh = hy0+row-1, gw = wx0+col-1;
    float v = 0.f;
    if (gh>=0 && gh<IMG && gw>=0 && gw<IMG)
      v = g_h1[((size_t)(b*IMG+gh)*IMG+gw)*36 + ci];
    ins[(row*18+col)*37+ci] = v;
  }
  for (int t=tid;t<9*36*36;t+=256) wsh[t] = w2[t];
  __syncthreads();
  int tx = tid&15, ty = tid>>4;
  float acc[36];
#pragma unroll
  for (int co=0;co<36;co++) acc[co] = b2[co];
  for (int dy=0;dy<3;dy++)
    for (int dx=0;dx<3;dx++){
      const float* wp = wsh + (dy*3+dx)*36*36;
      const float* ip = ins + ((ty+dy)*18 + tx+dx)*37;
      for (int ci=0;ci<36;ci++){
        float v = ip[ci];
        const float* wr = wp + ci*36;
#pragma unroll
        for (int co=0;co<36;co++) acc[co] += v*wr[co];
      }
    }
  size_t o = ((size_t)(b*IMG+hy0+ty)*IMG + wx0+tx)*36;
  float4* dst = (float4*)(g_h2 + o);
#pragma unroll
  for (int q=0;q<9;q++){
    float4 r; r.x=lrelu(acc[q*4]); r.y=lrelu(acc[q*4+1]); r.z=lrelu(acc[q*4+2]); r.w=lrelu(acc[q*4+3]);
    dst[q]=r;
  }
}

// =============== K3: qv = (h2@w3+b3) * (x@lw+lb), NHWC out ===============
// 64 pixels/block, thread tile 4px x 12co (co = tx + 16j)
__global__ void __launch_bounds__(256) k_qv(const float* __restrict__ x,
                                            const float* __restrict__ w3, const float* __restrict__ b3,
                                            const float* __restrict__ lw, const float* __restrict__ lb){
  extern __shared__ float sm3[];
  float* Hs  = sm3;            // 64*37 = 2368
  float* W3s = sm3 + 2368;     // 36*192 = 6912
  float* Xs  = W3s + 6912;     // 2368
  float* Wls = Xs + 2368;      // 6912   total 18560 floats = 74240 B
  int tid = threadIdx.x; int tx = tid&15; int ty = tid>>4;
  int r0 = blockIdx.x*64; int b = r0>>16; int p0 = r0&65535;
  float ah[4][12], al[4][12];
#pragma unroll
  for (int i=0;i<4;i++)
#pragma unroll
    for (int j=0;j<12;j++){ ah[i][j]=0.f; al[i][j]=0.f; }

  // h3 GEMM (K=36)
  for (int t=tid;t<64*36;t+=256){ int px=t/36, ci=t-px*36; Hs[px*37+ci] = g_h2[(size_t)(r0+px)*36+ci]; }
  for (int t=tid;t<36*192;t+=256){ int k=t/192, co=t-k*192; W3s[t] = (co<180)? w3[k*180+co] : 0.f; }
  __syncthreads();
  for (int k=0;k<36;k++){
    float a[4];
#pragma unroll
    for (int i=0;i<4;i++) a[i]=Hs[(ty+16*i)*37+k];
    float bb[12];
#pragma unroll
    for (int j=0;j<12;j++) bb[j]=W3s[k*192+tx+16*j];
#pragma unroll
    for (int i=0;i<4;i++)
#pragma unroll
      for (int j=0;j<12;j++) ah[i][j] += a[i]*bb[j];
  }

  // lin GEMM (K=180, 5 chunks of 36)
  for (int kc=0;kc<5;kc++){
    __syncthreads();
    int k0 = kc*36;
    for (int t=tid;t<64*36;t+=256){ int ci=t>>6, px=t&63;
      Xs[px*37+ci] = x[((size_t)(b*180+k0+ci))*NPIX + p0+px]; }
    for (int t=tid;t<36*192;t+=256){ int k=t/192, co=t-k*192; Wls[t] = (co<180)? lw[(k0+k)*180+co] : 0.f; }
    __syncthreads();
    for (int k=0;k<36;k++){
      float a[4];
#pragma unroll
      for (int i=0;i<4;i++) a[i]=Xs[(ty+16*i)*37+k];
      float bb[12];
#pragma unroll
      for (int j=0;j<12;j++) bb[j]=Wls[k*192+tx+16*j];
#pragma unroll
      for (int i=0;i<4;i++)
#pragma unroll
        for (int j=0;j<12;j++) al[i][j] += a[i]*bb[j];
    }
  }

#pragma unroll
  for (int j=0;j<12;j++){
    int co = tx + 16*j;
    if (co < 180){
      float bb3 = b3[co], blb = lb[co];
#pragma unroll
      for (int i=0;i<4;i++){
        size_t row = (size_t)(r0 + ty + 16*i);
        g_qv[row*180 + co] = (ah[i][j]+bb3)*(al[i][j]+blb);
      }
    }
  }
}

// =============== K4: per-window attention (spatial + channel) ===============
// one block per window (1024), 256 threads; smem = QS[256*91] + VS[256*91] + SC[8192]
__global__ void __launch_bounds__(256) k_attn(const float* __restrict__ sl_w,
                                              const float* __restrict__ sl_b){
  extern __shared__ float sm4[];
  float* QS = sm4;                // stride 91
  float* VS = sm4 + 256*91;
  float* SC = sm4 + 2*256*91;     // vp (5760) then cmap (8100)
  int tid = threadIdx.x;
  int bw = blockIdx.x;
  int b = bw>>8, wy = (bw>>4)&15, wx = bw&15;
  int l = tid;
  int gh = wy*16 + (l>>4), gw = wx*16 + (l&15);
  size_t pix = ((size_t)(b*IMG+gh))*IMG + gw;

  // ---- P1: load q,v ----
  {
    const float4* src = (const float4*)(g_qv + pix*180);
#pragma unroll
    for (int k=0;k<45;k++){
      float4 v4 = src[k];
      int c0 = k*4;
      float vals[4] = {v4.x,v4.y,v4.z,v4.w};
#pragma unroll
      for (int e=0;e<4;e++){
        int c = c0+e;
        if (c < 90) QS[l*91+c] = vals[e];
        else        VS[l*91+(c-90)] = vals[e];
      }
    }
  }
  __syncthreads();

  // ---- P2: vp[nh][m][hd] = weighted 2x2 pool of v ----
  float slw0=sl_w[0], slw1=sl_w[1], slw2=sl_w[2], slw3=sl_w[3], slb=sl_b[0];
  for (int idx=tid; idx<5760; idx+=256){
    int nh = idx/960; int r = idx - nh*960; int m = r/15; int hd = r - m*15;
    int mh = m>>3, mw = m&7; int ch = nh*15+hd;
    int l00 = (mh*2)*16 + mw*2;
    SC[idx] = slb + slw0*VS[l00*91+ch]     + slw1*VS[(l00+1)*91+ch]
                  + slw2*VS[(l00+16)*91+ch] + slw3*VS[(l00+17)*91+ch];
  }
  __syncthreads();

  // ---- P4: corr = q.vp/15 + rpb ; xs = corr@vp -> g_y[:, 0:90] ----
  {
    float* ydst = g_y + pix*180;
    for (int nh=0; nh<6; nh++){
      float q[15];
#pragma unroll
      for (int hd=0;hd<15;hd++) q[hd] = QS[l*91 + nh*15 + hd];
      const float* vp = SC + nh*960;
      const float* rpbrow = g_rpb + ((size_t)(nh*256 + l))*64;
      float xs[15];
#pragma unroll
      for (int hd=0;hd<15;hd++) xs[hd]=0.f;
      for (int m0=0;m0<64;m0+=16){
        float corr[16];
#pragma unroll
        for (int mm=0;mm<16;mm++){
          const float* vpm = vp + (m0+mm)*15;
          float s = 0.f;
#pragma unroll
          for (int hd=0;hd<15;hd++) s += q[hd]*vpm[hd];
          corr[mm] = s*(1.f/15.f) + rpbrow[m0+mm];
        }
#pragma unroll
        for (int mm=0;mm<16;mm++){
          const float* vpm = vp + (m0+mm)*15;
#pragma unroll
          for (int hd=0;hd<15;hd++) xs[hd] += corr[mm]*vpm[hd];
        }
      }
#pragma unroll
      for (int hd=0;hd<15;hd++) ydst[nh*15+hd] = xs[hd];
    }
  }

  // ---- P3: cmap 6x6 register tiles (225 active threads) ----
  float cm[6][6];
  int cb=0, db=0;
  bool act = (tid < 225);
  if (act){
    cb = (tid/15)*6; db = (tid%15)*6;
#pragma unroll
    for (int i=0;i<6;i++)
#pragma unroll
      for (int j=0;j<6;j++) cm[i][j]=0.f;
    for (int ll=0; ll<256; ll++){
      float qr[6], vr[6];
#pragma unroll
      for (int i=0;i<6;i++) qr[i] = QS[ll*91+cb+i];
#pragma unroll
      for (int j=0;j<6;j++) vr[j] = VS[ll*91+db+j];
#pragma unroll
      for (int i=0;i<6;i++)
#pragma unroll
        for (int j=0;j<6;j++) cm[i][j] += qr[i]*vr[j];
    }
  }
  __syncthreads();   // vp reads (P4) and QS/VS reads (P3) done -> safe to overwrite SC
  if (act){
#pragma unroll
    for (int i=0;i<6;i++)
#pragma unroll
      for (int j=0;j<6;j++) SC[(cb+i)*90 + db+j] = cm[i][j]*(1.f/256.f);
  }
  __syncthreads();

  // ---- P6: xc[l,c] = sum_d cmap[c,d]*v[l,d] -> g_y[:, 90:180] ----
  {
    float* ydst = g_y + pix*180 + 90;
    for (int c0=0;c0<90;c0+=10){
      float s[10];
#pragma unroll
      for (int i=0;i<10;i++) s[i]=0.f;
      for (int d=0; d<90; d++){
        float vv = VS[l*91+d];
#pragma unroll
        for (int i=0;i<10;i++) s[i] += SC[(c0+i)*90+d]*vv;
      }
#pragma unroll
      for (int i=0;i<10;i++) ydst[c0+i] = s[i];
    }
  }
}

// =============== K5: out = x + RMSNorm(y@proj_w + proj_b)*norm_w, NCHW out ===============
// 64 pixels/block, 240 threads (16 px-lanes x 15 co-groups), thread tile 4px x 12co
__global__ void __launch_bounds__(240) k_proj(const float* __restrict__ x,
                                              const float* __restrict__ pw,
                                              const float* __restrict__ pb,
                                              const float* __restrict__ nw,
                                              float* __restrict__ out){
  __shared__ float As[64*37];
  __shared__ float Bs[36*180];
  __shared__ float red[15*64];
  __shared__ float scl[64];
  int tid = threadIdx.x; int tx = tid&15; int ty = tid>>4;  // ty in [0,15)
  int r0 = blockIdx.x*64; int b = r0>>16; int p0 = r0&65535;
  float acc[4][12];
#pragma unroll
  for (int i=0;i<4;i++)
#pragma unroll
    for (int j=0;j<12;j++) acc[i][j]=0.f;

  for (int kc=0;kc<5;kc++){
    int k0 = kc*36;
    for (int t=tid;t<64*36;t+=240){ int px=t/36, ci=t-px*36; As[px*37+ci] = g_y[(size_t)(r0+px)*180 + k0+ci]; }
    for (int t=tid;t<36*180;t+=240) Bs[t] = pw[(size_t)k0*180 + t];
    __syncthreads();
    for (int k=0;k<36;k++){
      float a[4];
#pragma unroll
      for (int i=0;i<4;i++) a[i]=As[(tx+16*i)*37+k];
      float bb[12];
#pragma unroll
      for (int j=0;j<12;j++) bb[j]=Bs[k*180 + ty*12 + j];
#pragma unroll
      for (int i=0;i<4;i++)
#pragma unroll
        for (int j=0;j<12;j++) acc[i][j] += a[i]*bb[j];
    }
    __syncthreads();
  }

  float pbr[12];
#pragma unroll
  for (int j=0;j<12;j++) pbr[j] = pb[ty*12+j];
#pragma unroll
  for (int i=0;i<4;i++){
    float ss=0.f;
#pragma unroll
    for (int j=0;j<12;j++){ acc[i][j]+=pbr[j]; ss += acc[i][j]*acc[i][j]; }
    red[ty*64 + tx + 16*i] = ss;
  }
  __syncthreads();
  if (tid < 64){
    float s=0.f;
#pragma unroll
    for (int t=0;t<15;t++) s += red[t*64+tid];
    scl[tid] = rsqrtf(s*(1.f/180.f) + 1.1920929e-07f);
  }
  __syncthreads();
#pragma unroll
  for (int i=0;i<4;i++){
    int px = tx + 16*i;
    float sc = scl[px];
    size_t p = (size_t)(p0+px);
#pragma unroll
    for (int j=0;j<12;j++){
      int co = ty*12+j;
      size_t a = ((size_t)(b*180+co))*NPIX + p;
      out[a] = x[a] + acc[i][j]*sc*nw[co];
    }
  }
}

// =============== launch ===============
extern "C" void kernel_launch(void* const* d_in, const int* in_sizes, int n_in,
                              void* d_out, int out_size){
  const float* x     = (const float*)d_in[0];
  const float* w1    = (const float*)d_in[1];
  const float* b1    = (const float*)d_in[2];
  const float* w2    = (const float*)d_in[3];
  const float* b2    = (const float*)d_in[4];
  const float* w3    = (const float*)d_in[5];
  const float* b3    = (const float*)d_in[6];
  const float* lw    = (const float*)d_in[7];
  const float* lb    = (const float*)d_in[8];
  const float* sl_w  = (const float*)d_in[9];
  const float* sl_b  = (const float*)d_in[10];
  const float* ppw   = (const float*)d_in[11];
  const float* ppb   = (const float*)d_in[12];
  const float* ln1w  = (const float*)d_in[13];
  const float* ln1b  = (const float*)d_in[14];
  const float* l1w   = (const float*)d_in[15];
  const float* l1b   = (const float*)d_in[16];
  const float* ln2w  = (const float*)d_in[17];
  const float* ln2b  = (const float*)d_in[18];
  const float* l2w   = (const float*)d_in[19];
  const float* l2b   = (const float*)d_in[20];
  const float* ln3w  = (const float*)d_in[21];
  const float* ln3b  = (const float*)d_in[22];
  const float* l3w   = (const float*)d_in[23];
  const float* l3b   = (const float*)d_in[24];
  const float* pjw   = (const float*)d_in[25];
  const float* pjb   = (const float*)d_in[26];
  const float* nrmw  = (const float*)d_in[27];
  float* out = (float*)d_out;

  const int SM_K2 = (11988 + 11664) * 4;           // 94608 B
  const int SM_K3 = 18560 * 4;                     // 74240 B
  const int SM_K4 = (2*256*91 + 8192) * 4;         // 219136 B
  cudaFuncSetAttribute(k_conv3, cudaFuncAttributeMaxDynamicSharedMemorySize, SM_K2);
  cudaFuncSetAttribute(k_qv,    cudaFuncAttributeMaxDynamicSharedMemorySize, SM_K3);
  cudaFuncSetAttribute(k_attn,  cudaFuncAttributeMaxDynamicSharedMemorySize, SM_K4);

  k_pos<<<4,256>>>(ppw, ppb, ln1w, ln1b, l1w, l1b, ln2w, ln2b, l2w, l2b, ln3w, ln3b, l3w, l3b);
  k_rpb<<<384,256>>>();
  k_dfe1<<<TOTPIX/256,256>>>(x, w1, b1);
  k_conv3<<<dim3(16,16,4),256,SM_K2>>>(w2, b2);
  k_qv<<<TOTPIX/64,256,SM_K3>>>(x, w3, b3, lw, lb);
  k_attn<<<NWIN,256,SM_K4>>>(sl_w, sl_b);
  k_proj<<<TOTPIX/64,240>>>(x, pjw, pjb, nrmw, out);
}

// round 3
// speedup vs baseline: 1.1335x; 1.1335x over previous
#include <cuda_runtime.h>
#include <math.h>
#include <stdint.h>

#define NBATCH 4
#define NCH    180
#define IMG    256
#define NPIX   (IMG*IMG)            // 65536
#define TOTPIX (NBATCH*NPIX)        // 262144
#define MIDC   36
#define NHEAD  6
#define HDIM   15
#define WL     256
#define NWIN   1024

// ---- scratch (device globals; no allocation allowed) ----
__device__ float g_h1[(size_t)TOTPIX*MIDC];
__device__ float g_h2[(size_t)TOTPIX*MIDC];
__device__ float g_qv[(size_t)TOTPIX*NCH];
__device__ float g_y [(size_t)TOTPIX*NCH];
__device__ float g_pos[961*6];
__device__ float g_rpb[6*256*64];

typedef unsigned long long u64;

__device__ __forceinline__ u64 pk2(float lo, float hi){
  u64 r; asm("mov.b64 %0,{%1,%2};" : "=l"(r) : "f"(lo), "f"(hi)); return r;
}
__device__ __forceinline__ u64 dup2(float v){ return pk2(v, v); }
__device__ __forceinline__ void up2(u64 v, float& lo, float& hi){
  asm("mov.b64 {%0,%1},%2;" : "=f"(lo), "=f"(hi) : "l"(v));
}
__device__ __forceinline__ u64 ffma2(u64 a, u64 b, u64 c){
  u64 d; asm("fma.rn.f32x2 %0,%1,%2,%3;" : "=l"(d) : "l"(a), "l"(b), "l"(c)); return d;
}
__device__ __forceinline__ u64 fadd2(u64 a, u64 b){
  u64 d; asm("add.rn.f32x2 %0,%1,%2;" : "=l"(d) : "l"(a), "l"(b)); return d;
}
__device__ __forceinline__ u64 fmul2(u64 a, u64 b){
  u64 d; asm("mul.rn.f32x2 %0,%1,%2;" : "=l"(d) : "l"(a), "l"(b)); return d;
}

__device__ __forceinline__ float lrelu(float v){ return v >= 0.f ? v : 0.2f*v; }

// =============== K0a: position-bias MLP (961 rows) ===============
__device__ __forceinline__ void ln_relu11(const float* in, const float* w, const float* b, float* out){
  float m = 0.f;
#pragma unroll
  for (int j=0;j<11;j++) m += in[j];
  m *= (1.f/11.f);
  float var = 0.f;
#pragma unroll
  for (int j=0;j<11;j++){ float d = in[j]-m; var += d*d; }
  var *= (1.f/11.f);
  float inv = rsqrtf(var + 1e-5f);
#pragma unroll
  for (int j=0;j<11;j++) out[j] = fmaxf((in[j]-m)*inv*w[j] + b[j], 0.f);
}

__global__ void k_pos(const float* __restrict__ pw, const float* __restrict__ pb,
                      const float* __restrict__ ln1w, const float* __restrict__ ln1b,
                      const float* __restrict__ w1,  const float* __restrict__ b1,
                      const float* __restrict__ ln2w, const float* __restrict__ ln2b,
                      const float* __restrict__ w2,  const float* __restrict__ b2,
                      const float* __restrict__ ln3w, const float* __restrict__ ln3b,
                      const float* __restrict__ w3,  const float* __restrict__ b3){
  int n = blockIdx.x*blockDim.x + threadIdx.x;
  if (n >= 961) return;
  float i0 = (float)(n/31) - 15.f;
  float i1 = (float)(n%31) - 15.f;
  float p[11], t[11];
#pragma unroll
  for (int j=0;j<11;j++) p[j] = i0*pw[j] + i1*pw[11+j] + pb[j];
  ln_relu11(p, ln1w, ln1b, t);
#pragma unroll
  for (int k=0;k<11;k++){ float s=b1[k];
#pragma unroll
    for (int j=0;j<11;j++) s += t[j]*w1[j*11+k]; p[k]=s; }
  ln_relu11(p, ln2w, ln2b, t);
#pragma unroll
  for (int k=0;k<11;k++){ float s=b2[k];
#pragma unroll
    for (int j=0;j<11;j++) s += t[j]*w2[j*11+k]; p[k]=s; }
  ln_relu11(p, ln3w, ln3b, t);
#pragma unroll
  for (int k=0;k<6;k++){ float s=b3[k];
#pragma unroll
    for (int j=0;j<11;j++) s += t[j]*w3[j*6+k];
    g_pos[n*6+k] = s; }
}

// =============== K0b: rpb[nh][l][m] = mean over 2x2 of pos ===============
__global__ void k_rpb(){
  int idx = blockIdx.x*blockDim.x + threadIdx.x;
  if (idx >= 6*256*64) return;
  int nh = idx/16384;
  int r  = idx - nh*16384;
  int l  = r>>6;
  int m  = r&63;
  int rl = l>>4, cl = l&15;
  int mh = m>>3, mw = m&7;
  float s = 0.f;
#pragma unroll
  for (int rh=0;rh<2;rh++)
#pragma unroll
    for (int rw=0;rw<2;rw++){
      int r2 = mh*2+rh, c2 = mw*2+rw;
      int k = (rl-r2+15)*31 + (cl-c2+15);
      s += g_pos[k*6+nh];
    }
  g_rpb[idx] = 0.25f*s;
}

// =============== K1: h1 = lrelu(x @ w1 + b1), 180->36, NCHW in, NHWC out ===============
__global__ void __launch_bounds__(256) k_dfe1(const float* __restrict__ x,
                                              const float* __restrict__ w1,
                                              const float* __restrict__ b1){
  __shared__ __align__(16) float ws[180*36];
  int tid = threadIdx.x;
  for (int t=tid;t<180*36;t+=256) ws[t]=w1[t];
  __syncthreads();
  int r = blockIdx.x*256 + tid;
  int b = r>>16; int p = r&65535;
  const float* xp = x + (size_t)b*NCH*NPIX + p;
  u64 acc2[18];
#pragma unroll
  for (int q=0;q<18;q++) acc2[q] = pk2(b1[2*q], b1[2*q+1]);
  for (int ci=0;ci<180;ci++){
    u64 v2 = dup2(xp[(size_t)ci*NPIX]);
    const ulonglong2* wr = (const ulonglong2*)(ws + ci*36);
#pragma unroll
    for (int q=0;q<9;q++){
      ulonglong2 w = wr[q];
      acc2[2*q]   = ffma2(v2, w.x, acc2[2*q]);
      acc2[2*q+1] = ffma2(v2, w.y, acc2[2*q+1]);
    }
  }
  float2* dst = (float2*)(g_h1 + (size_t)r*36);
#pragma unroll
  for (int q=0;q<18;q++){
    float lo,hi; up2(acc2[q], lo, hi);
    dst[q] = make_float2(lrelu(lo), lrelu(hi));
  }
}

// =============== K2: h2 = lrelu(conv3x3(h1)), 36->36, NHWC ===============
__global__ void __launch_bounds__(256) k_conv3(const float* __restrict__ w2,
                                               const float* __restrict__ b2){
  extern __shared__ float sm2[];
  float* ins = sm2;             // 18*18*37 = 11988 floats
  float* wsh = sm2 + 11988;     // 9*36*36  = 11664 floats (byte off 47952, 16-aligned)
  int tid = threadIdx.x;
  int b = blockIdx.z; int hy0 = blockIdx.y*16, wx0 = blockIdx.x*16;
  for (int t=tid;t<18*18*36;t+=256){
    int ci = t%36; int rc = t/36; int col = rc%18; int row = rc/18;
    int gh = hy0+row-1, gw = wx0+col-1;
    float v = 0.f;
    if (gh>=0 && gh<IMG && gw>=0 && gw<IMG)
      v = g_h1[((size_t)(b*IMG+gh)*IMG+gw)*36 + ci];
    ins[(row*18+col)*37+ci] = v;
  }
  for (int t=tid;t<9*36*36;t+=256) wsh[t] = w2[t];
  __syncthreads();
  int tx = tid&15, ty = tid>>4;
  u64 acc2[18];
#pragma unroll
  for (int q=0;q<18;q++) acc2[q] = pk2(b2[2*q], b2[2*q+1]);
  for (int dy=0;dy<3;dy++)
    for (int dx=0;dx<3;dx++){
      const float* wp = wsh + (dy*3+dx)*36*36;
      const float* ip = ins + ((ty+dy)*18 + tx+dx)*37;
      for (int ci=0;ci<36;ci++){
        u64 v2 = dup2(ip[ci]);
        const ulonglong2* wr = (const ulonglong2*)(wp + ci*36);
#pragma unroll
        for (int q=0;q<9;q++){
          ulonglong2 w = wr[q];
          acc2[2*q]   = ffma2(v2, w.x, acc2[2*q]);
          acc2[2*q+1] = ffma2(v2, w.y, acc2[2*q+1]);
        }
      }
    }
  size_t o = ((size_t)(b*IMG+hy0+ty)*IMG + wx0+tx)*36;
  float2* dst = (float2*)(g_h2 + o);
#pragma unroll
  for (int q=0;q<18;q++){
    float lo,hi; up2(acc2[q], lo, hi);
    dst[q] = make_float2(lrelu(lo), lrelu(hi));
  }
}

// =============== K3: qv = (h2@w3+b3) * (x@lw+lb), NHWC out ===============
// 64 pixels/block; thread owns 4 px (ty+16i) x 6 channel-pairs (co = 32j+2tx+{0,1})
__global__ void __launch_bounds__(256) k_qv(const float* __restrict__ x,
                                            const float* __restrict__ w3, const float* __restrict__ b3,
                                            const float* __restrict__ lw, const float* __restrict__ lb){
  extern __shared__ float sm3[];
  float* Hs  = sm3;            // 64*37 = 2368
  float* W3s = sm3 + 2368;     // 36*192 = 6912 (byte off 9472, 16-aligned)
  float* Xs  = W3s + 6912;     // 2368
  float* Wls = Xs + 2368;      // 6912
  int tid = threadIdx.x; int tx = tid&15; int ty = tid>>4;
  int r0 = blockIdx.x*64; int b = r0>>16; int p0 = r0&65535;
  u64 ah2[4][6], al2[4][6];
#pragma unroll
  for (int i=0;i<4;i++)
#pragma unroll
    for (int j=0;j<6;j++){ ah2[i][j]=0ull; al2[i][j]=0ull; }

  // GEMM1 (K=36)
  for (int t=tid;t<64*36;t+=256){ int px=t/36, ci=t-px*36; Hs[px*37+ci] = g_h2[(size_t)(r0+px)*36+ci]; }
  for (int t=tid;t<36*192;t+=256){ int k=t/192, co=t-k*192; W3s[t] = (co<180)? w3[k*180+co] : 0.f; }
  __syncthreads();
  for (int k=0;k<36;k++){
    u64 a2[4];
#pragma unroll
    for (int i=0;i<4;i++) a2[i] = dup2(Hs[(ty+16*i)*37+k]);
    u64 bb[6];
#pragma unroll
    for (int j=0;j<6;j++) bb[j] = *(const u64*)(W3s + k*192 + 32*j + 2*tx);
#pragma unroll
    for (int i=0;i<4;i++)
#pragma unroll
      for (int j=0;j<6;j++) ah2[i][j] = ffma2(a2[i], bb[j], ah2[i][j]);
  }

  // GEMM2 (K=180, 5 chunks)
  for (int kc=0;kc<5;kc++){
    __syncthreads();
    int k0 = kc*36;
    for (int t=tid;t<64*36;t+=256){ int ci=t>>6, px=t&63;
      Xs[px*37+ci] = x[((size_t)(b*180+k0+ci))*NPIX + p0+px]; }
    for (int t=tid;t<36*192;t+=256){ int k=t/192, co=t-k*192; Wls[t] = (co<180)? lw[(k0+k)*180+co] : 0.f; }
    __syncthreads();
    for (int k=0;k<36;k++){
      u64 a2[4];
#pragma unroll
      for (int i=0;i<4;i++) a2[i] = dup2(Xs[(ty+16*i)*37+k]);
      u64 bb[6];
#pragma unroll
      for (int j=0;j<6;j++) bb[j] = *(const u64*)(Wls + k*192 + 32*j + 2*tx);
#pragma unroll
      for (int i=0;i<4;i++)
#pragma unroll
        for (int j=0;j<6;j++) al2[i][j] = ffma2(a2[i], bb[j], al2[i][j]);
    }
  }

#pragma unroll
  for (int j=0;j<6;j++){
    int co0 = 32*j + 2*tx;
    if (co0 < 180){
      float2 t3 = *(const float2*)(b3+co0);
      float2 tl = *(const float2*)(lb+co0);
      u64 b3v = pk2(t3.x, t3.y), lbv = pk2(tl.x, tl.y);
#pragma unroll
      for (int i=0;i<4;i++){
        u64 r = fmul2(fadd2(ah2[i][j], b3v), fadd2(al2[i][j], lbv));
        float lo,hi; up2(r, lo, hi);
        size_t row = (size_t)(r0 + ty + 16*i);
        *(float2*)(g_qv + row*180 + co0) = make_float2(lo, hi);
      }
    }
  }
}

// =============== K4: per-window attention (spatial + channel) ===============
// smem = QS[256*91] + VS[256*91] + SC[8280]; vp stride 16 (padded), cmap transposed stride 92
__global__ void __launch_bounds__(256) k_attn(const float* __restrict__ sl_w,
                                              const float* __restrict__ sl_b){
  extern __shared__ float sm4[];
  float* QS = sm4;
  float* VS = sm4 + 256*91;
  float* SC = sm4 + 2*256*91;     // vp: 6*64*16 = 6144 ; later cmap^T: 90*92 = 8280
  int tid = threadIdx.x;
  int bw = blockIdx.x;
  int b = bw>>8, wy = (bw>>4)&15, wx = bw&15;
  int l = tid;
  int gh = wy*16 + (l>>4), gw = wx*16 + (l&15);
  size_t pix = ((size_t)(b*IMG+gh))*IMG + gw;

  // ---- P1: load q,v ----
  {
    const float4* src = (const float4*)(g_qv + pix*180);
#pragma unroll
    for (int k=0;k<45;k++){
      float4 v4 = src[k];
      int c0 = k*4;
      float vals[4] = {v4.x,v4.y,v4.z,v4.w};
#pragma unroll
      for (int e=0;e<4;e++){
        int c = c0+e;
        if (c < 90) QS[l*91+c] = vals[e];
        else        VS[l*91+(c-90)] = vals[e];
      }
    }
  }
  __syncthreads();

  // ---- P2: vp[nh][m][16] (hd 0..14, pad 15 = 0) ----
  float slw0=sl_w[0], slw1=sl_w[1], slw2=sl_w[2], slw3=sl_w[3], slb=sl_b[0];
  for (int idx=tid; idx<6144; idx+=256){
    int nh = idx>>10; int r = idx & 1023; int m = r>>4; int hd = r&15;
    float val = 0.f;
    if (hd < 15){
      int mh = m>>3, mw = m&7; int ch = nh*15+hd;
      int l00 = (mh*2)*16 + mw*2;
      val = slb + slw0*VS[l00*91+ch]      + slw1*VS[(l00+1)*91+ch]
                + slw2*VS[(l00+16)*91+ch] + slw3*VS[(l00+17)*91+ch];
    }
    SC[idx] = val;
  }
  __syncthreads();

  // ---- P4: corr = q.vp/15 + rpb ; xs = corr@vp -> g_y[:, 0:90] ----
  {
    float* ydst = g_y + pix*180;
    for (int nh=0; nh<6; nh++){
      float qs[15];
#pragma unroll
      for (int hd=0;hd<15;hd++) qs[hd] = QS[l*91 + nh*15 + hd];
      u64 q2[8];
#pragma unroll
      for (int p=0;p<7;p++) q2[p] = pk2(qs[2*p], qs[2*p+1]);
      q2[7] = pk2(qs[14], 0.f);
      const float* vp = SC + (nh<<10);
      const float* rpbrow = g_rpb + ((size_t)((nh<<8) + l))*64;
      u64 xs2[8];
#pragma unroll
      for (int p=0;p<8;p++) xs2[p]=0ull;
      for (int m0=0;m0<64;m0+=4){
        float4 rb = *(const float4*)(rpbrow + m0);
        float rbv[4] = {rb.x, rb.y, rb.z, rb.w};
#pragma unroll
        for (int t=0;t<4;t++){
          const ulonglong2* vpp = (const ulonglong2*)(vp + ((m0+t)<<4));
          ulonglong2 wA = vpp[0], wB = vpp[1], wC = vpp[2], wD = vpp[3];
          u64 d2 = fmul2(q2[0], wA.x);
          d2 = ffma2(q2[1], wA.y, d2);
          d2 = ffma2(q2[2], wB.x, d2);
          d2 = ffma2(q2[3], wB.y, d2);
          d2 = ffma2(q2[4], wC.x, d2);
          d2 = ffma2(q2[5], wC.y, d2);
          d2 = ffma2(q2[6], wD.x, d2);
          d2 = ffma2(q2[7], wD.y, d2);
          float lo,hi; up2(d2, lo, hi);
          u64 s2 = dup2((lo+hi)*(1.f/15.f) + rbv[t]);
          xs2[0] = ffma2(s2, wA.x, xs2[0]);
          xs2[1] = ffma2(s2, wA.y, xs2[1]);
          xs2[2] = ffma2(s2, wB.x, xs2[2]);
          xs2[3] = ffma2(s2, wB.y, xs2[3]);
          xs2[4] = ffma2(s2, wC.x, xs2[4]);
          xs2[5] = ffma2(s2, wC.y, xs2[5]);
          xs2[6] = ffma2(s2, wD.x, xs2[6]);
          xs2[7] = ffma2(s2, wD.y, xs2[7]);
        }
      }
#pragma unroll
      for (int p=0;p<7;p++){
        float lo,hi; up2(xs2[p], lo, hi);
        ydst[nh*15+2*p] = lo; ydst[nh*15+2*p+1] = hi;
      }
      { float lo,hi; up2(xs2[7], lo, hi); ydst[nh*15+14] = lo; }
    }
  }

  // ---- P3: cmap 6x6 register tiles (225 active threads), j paired ----
  u64 cm2[6][3];
  int cb=0, db=0;
  bool act = (tid < 225);
  if (act){
    cb = (tid/15)*6; db = (tid%15)*6;
#pragma unroll
    for (int i=0;i<6;i++)
#pragma unroll
      for (int t=0;t<3;t++) cm2[i][t]=0ull;
    for (int ll=0; ll<256; ll++){
      u64 qr[6];
#pragma unroll
      for (int i=0;i<6;i++) qr[i] = dup2(QS[ll*91+cb+i]);
      u64 vr[3];
#pragma unroll
      for (int t=0;t<3;t++) vr[t] = pk2(VS[ll*91+db+2*t], VS[ll*91+db+2*t+1]);
#pragma unroll
      for (int i=0;i<6;i++)
#pragma unroll
        for (int t=0;t<3;t++) cm2[i][t] = ffma2(qr[i], vr[t], cm2[i][t]);
    }
  }
  __syncthreads();   // vp + QS/VS read phases done -> safe to overwrite SC with cmap^T
  if (act){
#pragma unroll
    for (int i=0;i<6;i++)
#pragma unroll
      for (int t=0;t<3;t++){
        float lo,hi; up2(cm2[i][t], lo, hi);
        // store TRANSPOSED: SC[d*92 + c]
        SC[(db+2*t  )*92 + cb+i] = lo*(1.f/256.f);
        SC[(db+2*t+1)*92 + cb+i] = hi*(1.f/256.f);
      }
  }
  __syncthreads();

  // ---- P6: xc[l,c] = sum_d cmap[c,d]*v[l,d], cmap^T rows give c-pairs ----
  {
    float* ydst = g_y + pix*180 + 90;
    for (int c0=0;c0<90;c0+=18){
      u64 s2[9];
#pragma unroll
      for (int t=0;t<9;t++) s2[t]=0ull;
      for (int d=0; d<90; d++){
        u64 v2 = dup2(VS[l*91+d]);
        const u64* cp = (const u64*)(SC + d*92 + c0);
#pragma unroll
        for (int t=0;t<9;t++) s2[t] = ffma2(v2, cp[t], s2[t]);
      }
#pragma unroll
      for (int t=0;t<9;t++){
        float lo,hi; up2(s2[t], lo, hi);
        ydst[c0+2*t] = lo; ydst[c0+2*t+1] = hi;
      }
    }
  }
}

// =============== K5: out = x + RMSNorm(y@proj_w + proj_b)*norm_w, NCHW out ===============
__global__ void __launch_bounds__(240) k_proj(const float* __restrict__ x,
                                              const float* __restrict__ pw,
                                              const float* __restrict__ pb,
                                              const float* __restrict__ nw,
                                              float* __restrict__ out){
  __shared__ __align__(16) float As[64*37];
  __shared__ __align__(16) float Bs[36*180];
  __shared__ float red[15*64];
  __shared__ float scl[64];
  int tid = threadIdx.x; int tx = tid&15; int ty = tid>>4;  // ty in [0,15)
  int r0 = blockIdx.x*64; int b = r0>>16; int p0 = r0&65535;
  u64 acc2[4][6];
#pragma unroll
  for (int i=0;i<4;i++)
#pragma unroll
    for (int j=0;j<6;j++) acc2[i][j]=0ull;

  for (int kc=0;kc<5;kc++){
    int k0 = kc*36;
    for (int t=tid;t<64*36;t+=240){ int px=t/36, ci=t-px*36; As[px*37+ci] = g_y[(size_t)(r0+px)*180 + k0+ci]; }
    for (int t=tid;t<36*180;t+=240) Bs[t] = pw[(size_t)k0*180 + t];
    __syncthreads();
    for (int k=0;k<36;k++){
      u64 a2[4];
#pragma unroll
      for (int i=0;i<4;i++) a2[i] = dup2(As[(tx+16*i)*37+k]);
      const ulonglong2* bp = (const ulonglong2*)(Bs + k*180 + ty*12);
      ulonglong2 b0 = bp[0], b1 = bp[1], b2v = bp[2];
      u64 bb[6] = {b0.x, b0.y, b1.x, b1.y, b2v.x, b2v.y};
#pragma unroll
      for (int i=0;i<4;i++)
#pragma unroll
        for (int j=0;j<6;j++) acc2[i][j] = ffma2(a2[i], bb[j], acc2[i][j]);
    }
    __syncthreads();
  }

  u64 pbp[6];
#pragma unroll
  for (int j=0;j<6;j++){
    float2 t2 = *(const float2*)(pb + ty*12 + 2*j);
    pbp[j] = pk2(t2.x, t2.y);
  }
#pragma unroll
  for (int i=0;i<4;i++){
    u64 sq = 0ull;
#pragma unroll
    for (int j=0;j<6;j++){
      acc2[i][j] = fadd2(acc2[i][j], pbp[j]);
      sq = ffma2(acc2[i][j], acc2[i][j], sq);
    }
    float lo,hi; up2(sq, lo, hi);
    red[ty*64 + tx + 16*i] = lo + hi;
  }
  __syncthreads();
  if (tid < 64){
    float s=0.f;
#pragma unroll
    for (int t=0;t<15;t++) s += red[t*64+tid];
    scl[tid] = rsqrtf(s*(1.f/180.f) + 1.1920929e-07f);
  }
  __syncthreads();
#pragma unroll
  for (int i=0;i<4;i++){
    int px = tx + 16*i;
    float sc = scl[px];
    size_t p = (size_t)(p0+px);
#pragma unroll
    for (int j=0;j<6;j++){
      float lo,hi; up2(acc2[i][j], lo, hi);
      int co = ty*12 + 2*j;
      size_t a0 = ((size_t)(b*180+co))*NPIX + p;
      size_t a1 = a0 + NPIX;
      out[a0] = x[a0] + lo*sc*nw[co];
      out[a1] = x[a1] + hi*sc*nw[co+1];
    }
  }
}

// =============== launch ===============
extern "C" void kernel_launch(void* const* d_in, const int* in_sizes, int n_in,
                              void* d_out, int out_size){
  const float* x     = (const float*)d_in[0];
  const float* w1    = (const float*)d_in[1];
  const float* b1    = (const float*)d_in[2];
  const float* w2    = (const float*)d_in[3];
  const float* b2    = (const float*)d_in[4];
  const float* w3    = (const float*)d_in[5];
  const float* b3    = (const float*)d_in[6];
  const float* lw    = (const float*)d_in[7];
  const float* lb    = (const float*)d_in[8];
  const float* sl_w  = (const float*)d_in[9];
  const float* sl_b  = (const float*)d_in[10];
  const float* ppw   = (const float*)d_in[11];
  const float* ppb   = (const float*)d_in[12];
  const float* ln1w  = (const float*)d_in[13];
  const float* ln1b  = (const float*)d_in[14];
  const float* l1w   = (const float*)d_in[15];
  const float* l1b   = (const float*)d_in[16];
  const float* ln2w  = (const float*)d_in[17];
  const float* ln2b  = (const float*)d_in[18];
  const float* l2w   = (const float*)d_in[19];
  const float* l2b   = (const float*)d_in[20];
  const float* ln3w  = (const float*)d_in[21];
  const float* ln3b  = (const float*)d_in[22];
  const float* l3w   = (const float*)d_in[23];
  const float* l3b   = (const float*)d_in[24];
  const float* pjw   = (const float*)d_in[25];
  const float* pjb   = (const float*)d_in[26];
  const float* nrmw  = (const float*)d_in[27];
  float* out = (float*)d_out;

  const int SM_K2 = (11988 + 11664) * 4;           // 94608 B
  const int SM_K3 = 18560 * 4;                     // 74240 B
  const int SM_K4 = (2*256*91 + 8280) * 4;         // 219488 B
  cudaFuncSetAttribute(k_conv3, cudaFuncAttributeMaxDynamicSharedMemorySize, SM_K2);
  cudaFuncSetAttribute(k_qv,    cudaFuncAttributeMaxDynamicSharedMemorySize, SM_K3);
  cudaFuncSetAttribute(k_attn,  cudaFuncAttributeMaxDynamicSharedMemorySize, SM_K4);

  k_pos<<<4,256>>>(ppw, ppb, ln1w, ln1b, l1w, l1b, ln2w, ln2b, l2w, l2b, ln3w, ln3b, l3w, l3b);
  k_rpb<<<384,256>>>();
  k_dfe1<<<TOTPIX/256,256>>>(x, w1, b1);
  k_conv3<<<dim3(16,16,4),256,SM_K2>>>(w2, b2);
  k_qv<<<TOTPIX/64,256,SM_K3>>>(x, w3, b3, lw, lb);
  k_attn<<<NWIN,256,SM_K4>>>(sl_w, sl_b);
  k_proj<<<TOTPIX/64,240>>>(x, pjw, pjb, nrmw, out);
}